// round 5
// baseline (speedup 1.0000x reference)
#include <cuda_runtime.h>
#include <cuda_bf16.h>
#include <math.h>
#include <cstdint>

#define Bn 4
#define Cc 256
#define Onc 256
#define Hh 64
#define Ww 64
#define Kk 9
#define HW 4096
#define KTOT (Cc * Kk)        /* 2304 */
#define CK 64
#define NCHUNK (KTOT / CK)    /* 36 */

typedef uint32_t u32;
typedef unsigned short USH;

// ---------------------------------------------------------------------------
// Global scratch
// ---------------------------------------------------------------------------
__device__ float g_buf1[Bn * Cc * HW];
__device__ float g_buf2[Bn * Cc * HW];
// bf16 split B images: [layer][part(hi,lo)][chunk][n][72]
__device__ __align__(16) USH g_bmain[3 * 2 * NCHUNK * Onc * 72];
__device__ __align__(16) USH g_boff [3 * 2 * NCHUNK * 32 * 72];

// ---------------------------------------------------------------------------
// PTX helpers (arch-agnostic: ldmatrix + mma.sync bf16, sm_80+)
// ---------------------------------------------------------------------------
__device__ __forceinline__ u32 smem_u32(const void* p) {
    u32 a;
    asm("{ .reg .u64 t; cvta.to.shared.u64 t, %1; cvt.u32.u64 %0, t; }" : "=r"(a) : "l"(p));
    return a;
}
#define LDSM4(r, addr) \
    asm volatile("ldmatrix.sync.aligned.m8n8.x4.shared.b16 {%0,%1,%2,%3}, [%4];" \
        : "=r"((r)[0]), "=r"((r)[1]), "=r"((r)[2]), "=r"((r)[3]) : "r"(addr))
#define LDSM2(r0, r1, addr) \
    asm volatile("ldmatrix.sync.aligned.m8n8.x2.shared.b16 {%0,%1}, [%2];" \
        : "=r"(r0), "=r"(r1) : "r"(addr))
#define MMA(d, a, b0, b1) \
    asm volatile("mma.sync.aligned.m16n8k16.row.col.f32.bf16.bf16.f32 " \
        "{%0,%1,%2,%3}, {%4,%5,%6,%7}, {%8,%9}, {%0,%1,%2,%3};" \
        : "+f"((d)[0]), "+f"((d)[1]), "+f"((d)[2]), "+f"((d)[3]) \
        : "r"((a)[0]), "r"((a)[1]), "r"((a)[2]), "r"((a)[3]), "r"(b0), "r"(b1))

__device__ __forceinline__ void split1(float v, USH& h, USH& l) {
    __nv_bfloat16 hb = __float2bfloat16_rn(v);
    float r = v - __bfloat162float(hb);
    __nv_bfloat16 lb = __float2bfloat16_rn(r);
    h = *(USH*)&hb;
    l = *(USH*)&lb;
}

// ---------------------------------------------------------------------------
// Prep kernels: build split-bf16 B images [part][chunk][n][72].
// K order: k' = tap*256 + c; chunk = k'/64, kk = k'%64.
// ---------------------------------------------------------------------------
__global__ void prep_bmain_kernel(const float* __restrict__ w, USH* __restrict__ dst)
{
    int idx = blockIdx.x * 256 + threadIdx.x;
    if (idx >= KTOT * Onc) return;
    int o  = idx & 255;
    int kp = idx >> 8;
    int c = kp & 255, tap = kp >> 8;
    float v = w[((size_t)o * Cc + c) * 9 + tap];
    USH h, l; split1(v, h, l);
    int chunk = kp >> 6, kk = kp & 63;
    dst[((size_t)chunk * Onc + o) * 72 + kk] = h;
    dst[((size_t)(NCHUNK + chunk) * Onc + o) * 72 + kk] = l;
}

__global__ void prep_boff_kernel(const float* __restrict__ w, USH* __restrict__ dst)
{
    int idx = blockIdx.x * 256 + threadIdx.x;
    if (idx >= KTOT * 32) return;
    int oc = idx & 31;
    int kp = idx >> 5;
    int c = kp & 255, tap = kp >> 8;
    float v = (oc < 27) ? w[((size_t)oc * Cc + c) * 9 + tap] : 0.f;
    USH h, l; split1(v, h, l);
    int chunk = kp >> 6, kk = kp & 63;
    dst[((size_t)chunk * 32 + oc) * 72 + kk] = h;
    dst[((size_t)(NCHUNK + chunk) * 32 + oc) * 72 + kk] = l;
}

// ---------------------------------------------------------------------------
// Fused DCN kernel via warp-MMA. 256 threads, tile 128 px (8x16) x 256 out.
// Grid (32, B). Smem layout (bytes):
//   A_HI 0       [128][72] bf16          (18432)
//   A_LO 18432                            (18432)
//   B_HI 36864   [256][72] bf16          (36864)
//   B_LO 73728                            (36864)
//   SIDX 110592  int4[9][128]            (18432)
//   SWGT 129024  float4[9][128]          (18432)
//   OM   147456  om[128][32] f32 / epilogue patches (16384)
//   total 163840
// ---------------------------------------------------------------------------
#define A_HI_O 0
#define A_LO_O 18432
#define B_HI_O 36864
#define B_LO_O 73728
#define SIDX_O 110592
#define SWGT_O 129024
#define OM_O   147456
#define SMEMSZ 163840

__global__ void __launch_bounds__(256, 1) dcn_mma_kernel(
    const float* __restrict__ x,
    const float* __restrict__ b_off,
    const USH* __restrict__ bmain,
    const USH* __restrict__ boff,
    const float* __restrict__ bias,
    float* __restrict__ out)
{
    extern __shared__ __align__(16) char smem[];
    USH*    Ahi  = (USH*)(smem + A_HI_O);
    USH*    Alo  = (USH*)(smem + A_LO_O);
    int4*   sidx = (int4*)(smem + SIDX_O);
    float4* swgt = (float4*)(smem + SWGT_O);
    float*  om   = (float*)(smem + OM_O);

    u32 sb  = smem_u32(smem);
    int tid = threadIdx.x, lane = tid & 31, wid = tid >> 5;
    int b = blockIdx.y, t = blockIdx.x;
    int py0 = (t >> 2) * 8, px0 = (t & 3) * 16;
    const float* xb = x + (size_t)b * Cc * HW;

    // ldmatrix lane-address components
    int lr = lane & 7, grp = lane >> 3;
    int a_row = lr + (grp & 1) * 8;       // A x4: +8 rows on odd grp
    int a_colb = (grp >> 1) * 16;         // A x4: +16B col on grp>=2
    int bp_row = lr + (grp >> 1) * 8;     // B x4 (2 n-tiles): +8 rows on grp>=2
    int bp_colb = (grp & 1) * 16;         // B x4: +16B col on odd grp

    // ======================= Phase 1: offset conv =======================
    {
        float d1[4][4];
#pragma unroll
        for (int i = 0; i < 4; i++)
#pragma unroll
            for (int q = 0; q < 4; q++) d1[i][q] = 0.f;
        int m0 = (wid & 1) * 64;
        int n0 = (wid >> 1) * 8;

        for (int j = 0; j < NCHUNK; j++) {
            int tap = j >> 2, c0 = (j & 3) << 6;
            int ty = tap / 3 - 1, tx = tap % 3 - 1;
            // A build: warp handles 8 channels x 128 px
#pragma unroll 2
            for (int ch = 0; ch < 8; ch++) {
                int c = wid * 8 + ch;
                const float* xc = xb + (size_t)(c0 + c) * HW;
#pragma unroll
                for (int pg = 0; pg < 4; pg++) {
                    int p = pg * 32 + lane;
                    int yy = py0 + (p >> 4) + ty;
                    int xx = px0 + (p & 15) + tx;
                    float v = 0.f;
                    if ((unsigned)yy < 64u && (unsigned)xx < 64u)
                        v = __ldg(xc + yy * 64 + xx);
                    USH h, l; split1(v, h, l);
                    Ahi[p * 72 + c] = h;
                    Alo[p * 72 + c] = l;
                }
            }
            // B staging [32][72] hi+lo
            {
                const uint4* s0 = (const uint4*)(boff + (size_t)j * (32 * 72));
                const uint4* s1 = (const uint4*)(boff + (size_t)(NCHUNK + j) * (32 * 72));
                for (int i = tid; i < 288; i += 256) {
                    ((uint4*)(smem + B_HI_O))[i] = s0[i];
                    ((uint4*)(smem + B_LO_O))[i] = s1[i];
                }
            }
            __syncthreads();
#pragma unroll
            for (int ks = 0; ks < 4; ks++) {
                int kb = ks * 32;
                u32 ah[4][4], al[4][4], bh[2], bl[2];
#pragma unroll
                for (int mt = 0; mt < 4; mt++) {
                    u32 aa = sb + A_HI_O + (u32)(m0 + mt * 16 + a_row) * 144 + kb + a_colb;
                    LDSM4(ah[mt], aa);
                    LDSM4(al[mt], aa + (A_LO_O - A_HI_O));
                }
                u32 ba = sb + B_HI_O + (u32)(n0 + (lane & 7)) * 144 + kb + ((lane >> 3) & 1) * 16;
                LDSM2(bh[0], bh[1], ba);
                LDSM2(bl[0], bl[1], ba + (B_LO_O - B_HI_O));
#pragma unroll
                for (int mt = 0; mt < 4; mt++) {
                    MMA(d1[mt], ah[mt], bh[0], bh[1]);
                    MMA(d1[mt], al[mt], bh[0], bh[1]);
                    MMA(d1[mt], ah[mt], bl[0], bl[1]);
                }
            }
            __syncthreads();
        }
        // write offset-conv result to om[128][32]
#pragma unroll
        for (int mt = 0; mt < 4; mt++) {
            int r = m0 + mt * 16 + (lane >> 2);
            int c2 = n0 + 2 * (lane & 3);
            om[r * 32 + c2]           = d1[mt][0];
            om[r * 32 + c2 + 1]       = d1[mt][1];
            om[(r + 8) * 32 + c2]     = d1[mt][2];
            om[(r + 8) * 32 + c2 + 1] = d1[mt][3];
        }
        __syncthreads();
    }

    // ============ Coordinates / gather weights (tid < 128) ============
    if (tid < 128) {
        int p = tid;
        int py = py0 + (p >> 4), px = px0 + (p & 15);
#pragma unroll
        for (int k = 0; k < 9; k++) {
            float dy = om[p * 32 + 2 * k]     + __ldg(b_off + 2 * k);
            float dx = om[p * 32 + 2 * k + 1] + __ldg(b_off + 2 * k + 1);
            float mr = om[p * 32 + 18 + k]    + __ldg(b_off + 18 + k);
            float mv = 1.f / (1.f + expf(-mr));
            float ysv = (float)py + (float)(k / 3 - 1) + dy;
            float xsv = (float)px + (float)(k % 3 - 1) + dx;
            float y0f = floorf(ysv), x0f = floorf(xsv);
            float wy = ysv - y0f, wx = xsv - x0f;
            int y0 = (int)y0f, x0 = (int)x0f;
            int y1 = y0 + 1, x1 = x0 + 1;
            bool vy0 = (y0 >= 0) && (y0 < Hh);
            bool vy1 = (y1 >= 0) && (y1 < Hh);
            bool vx0 = (x0 >= 0) && (x0 < Ww);
            bool vx1 = (x1 >= 0) && (x1 < Ww);
            int y0c = min(max(y0, 0), Hh - 1), y1c = min(max(y1, 0), Hh - 1);
            int x0c = min(max(x0, 0), Ww - 1), x1c = min(max(x1, 0), Ww - 1);
            float4 wv;
            wv.x = (vy0 && vx0) ? mv * (1.f - wy) * (1.f - wx) : 0.f;
            wv.y = (vy0 && vx1) ? mv * (1.f - wy) * wx         : 0.f;
            wv.z = (vy1 && vx0) ? mv * wy * (1.f - wx)         : 0.f;
            wv.w = (vy1 && vx1) ? mv * wy * wx                 : 0.f;
            int4 iv;
            iv.x = y0c * Ww + x0c;
            iv.y = y0c * Ww + x1c;
            iv.z = y1c * Ww + x0c;
            iv.w = y1c * Ww + x1c;
            sidx[k * 128 + p] = iv;
            swgt[k * 128 + p] = wv;
        }
    }
    __syncthreads();

    // ================= Phase 2: sampled GEMM (N=256) =================
    int m0 = (wid & 1) * 64;
    int n0 = (wid >> 1) * 64;
    float d2[4][8][4];
#pragma unroll
    for (int i = 0; i < 4; i++)
#pragma unroll
        for (int q = 0; q < 8; q++)
#pragma unroll
            for (int r = 0; r < 4; r++) d2[i][q][r] = 0.f;

    for (int j = 0; j < NCHUNK; j++) {
        int tap = j >> 2, c0 = (j & 3) << 6;
        const int4*   sx = sidx + tap * 128;
        const float4* sw = swgt + tap * 128;
#pragma unroll 2
        for (int ch = 0; ch < 8; ch++) {
            int c = wid * 8 + ch;
            const float* xc = xb + (size_t)(c0 + c) * HW;
#pragma unroll
            for (int pg = 0; pg < 4; pg++) {
                int p = pg * 32 + lane;
                int4   iv = sx[p];
                float4 wv = sw[p];
                float v = wv.x * __ldg(xc + iv.x) + wv.y * __ldg(xc + iv.y)
                        + wv.z * __ldg(xc + iv.z) + wv.w * __ldg(xc + iv.w);
                USH h, l; split1(v, h, l);
                Ahi[p * 72 + c] = h;
                Alo[p * 72 + c] = l;
            }
        }
        // B staging [256][72] hi+lo = 2304 uint4 each
        {
            const uint4* s0 = (const uint4*)(bmain + (size_t)j * (Onc * 72));
            const uint4* s1 = (const uint4*)(bmain + (size_t)(NCHUNK + j) * (Onc * 72));
            for (int i = tid; i < 2304; i += 256) {
                ((uint4*)(smem + B_HI_O))[i] = s0[i];
                ((uint4*)(smem + B_LO_O))[i] = s1[i];
            }
        }
        __syncthreads();
#pragma unroll
        for (int ks = 0; ks < 4; ks++) {
            int kb = ks * 32;
            u32 ah[4][4], al[4][4], bb[4][4];
#pragma unroll
            for (int mt = 0; mt < 4; mt++) {
                u32 aa = sb + A_HI_O + (u32)(m0 + mt * 16 + a_row) * 144 + kb + a_colb;
                LDSM4(ah[mt], aa);
                LDSM4(al[mt], aa + (A_LO_O - A_HI_O));
            }
#pragma unroll
            for (int np = 0; np < 4; np++) {
                u32 ba = sb + B_HI_O + (u32)(n0 + np * 16 + bp_row) * 144 + kb + bp_colb;
                LDSM4(bb[np], ba);
            }
#pragma unroll
            for (int mt = 0; mt < 4; mt++)
#pragma unroll
                for (int np = 0; np < 4; np++) {
                    MMA(d2[mt][2 * np],     ah[mt], bb[np][0], bb[np][1]);
                    MMA(d2[mt][2 * np + 1], ah[mt], bb[np][2], bb[np][3]);
                }
#pragma unroll
            for (int mt = 0; mt < 4; mt++)
#pragma unroll
                for (int np = 0; np < 4; np++) {
                    MMA(d2[mt][2 * np],     al[mt], bb[np][0], bb[np][1]);
                    MMA(d2[mt][2 * np + 1], al[mt], bb[np][2], bb[np][3]);
                }
#pragma unroll
            for (int np = 0; np < 4; np++) {
                u32 ba = sb + B_LO_O + (u32)(n0 + np * 16 + bp_row) * 144 + kb + bp_colb;
                LDSM4(bb[np], ba);
            }
#pragma unroll
            for (int mt = 0; mt < 4; mt++)
#pragma unroll
                for (int np = 0; np < 4; np++) {
                    MMA(d2[mt][2 * np],     ah[mt], bb[np][0], bb[np][1]);
                    MMA(d2[mt][2 * np + 1], ah[mt], bb[np][2], bb[np][3]);
                }
        }
        __syncthreads();
    }

    // ===================== Epilogue: bias + ReLU =====================
    {
        float* patch = om + wid * 512;   // [8 o][64 p] per warp
#pragma unroll 1
        for (int nt = 0; nt < 8; nt++) {
#pragma unroll
            for (int mt = 0; mt < 4; mt++) {
                int r = mt * 16 + (lane >> 2);
                int c2 = 2 * (lane & 3);
                patch[c2 * 64 + r]           = d2[mt][nt][0];
                patch[(c2 + 1) * 64 + r]     = d2[mt][nt][1];
                patch[c2 * 64 + r + 8]       = d2[mt][nt][2];
                patch[(c2 + 1) * 64 + r + 8] = d2[mt][nt][3];
            }
            __syncwarp();
#pragma unroll
            for (int orow = 0; orow < 8; orow++) {
                int o = n0 + nt * 8 + orow;
                float bv = __ldg(bias + o);
#pragma unroll
                for (int hf = 0; hf < 2; hf++) {
                    int p = m0 + hf * 32 + lane;
                    float v = patch[orow * 64 + hf * 32 + lane] + bv;
                    v = fmaxf(v, 0.f);
                    out[(size_t)(b * Onc + o) * HW + (py0 + (p >> 4)) * 64 + px0 + (p & 15)] = v;
                }
            }
            __syncwarp();
        }
    }
}

// ---------------------------------------------------------------------------
// Launch
// ---------------------------------------------------------------------------
extern "C" void kernel_launch(void* const* d_in, const int* in_sizes, int n_in,
                              void* d_out, int out_size)
{
    const float* x = (const float*)d_in[0];
    const float* w_off[3] = {(const float*)d_in[1], (const float*)d_in[5], (const float*)d_in[9]};
    const float* b_off[3] = {(const float*)d_in[2], (const float*)d_in[6], (const float*)d_in[10]};
    const float* wq[3]    = {(const float*)d_in[3], (const float*)d_in[7], (const float*)d_in[11]};
    const float* bias[3]  = {(const float*)d_in[4], (const float*)d_in[8], (const float*)d_in[12]};

    float *buf1, *buf2;
    USH *bm, *bo;
    cudaGetSymbolAddress((void**)&buf1, g_buf1);
    cudaGetSymbolAddress((void**)&buf2, g_buf2);
    cudaGetSymbolAddress((void**)&bm, g_bmain);
    cudaGetSymbolAddress((void**)&bo, g_boff);

    cudaFuncSetAttribute(dcn_mma_kernel, cudaFuncAttributeMaxDynamicSharedMemorySize, SMEMSZ);

    const size_t bm_l = (size_t)2 * NCHUNK * Onc * 72;
    const size_t bo_l = (size_t)2 * NCHUNK * 32 * 72;

    for (int l = 0; l < 3; l++) {
        prep_bmain_kernel<<<(KTOT * Onc + 255) / 256, 256>>>(wq[l], bm + l * bm_l);
        prep_boff_kernel<<<(KTOT * 32 + 255) / 256, 256>>>(w_off[l], bo + l * bo_l);
    }

    const float* src[3] = {x, buf1, buf2};
    float*       dst[3] = {buf1, buf2, (float*)d_out};

    for (int l = 0; l < 3; l++) {
        dcn_mma_kernel<<<dim3(32, Bn), 256, SMEMSZ>>>(src[l], b_off[l],
                                                      bm + l * bm_l, bo + l * bo_l,
                                                      bias[l], dst[l]);
    }
}

// round 6
// speedup vs baseline: 2.0111x; 2.0111x over previous
#include <cuda_runtime.h>
#include <math.h>
#include <cstdint>

#define Bn 4
#define Cc 256
#define Onc 256
#define Hh 64
#define Ww 64
#define Kk 9
#define HW 4096

typedef unsigned long long u64;

// Scratch (static device arrays — no allocation)
__device__ float g_buf1[Bn * Cc * HW];
__device__ float g_buf2[Bn * Cc * HW];
__device__ float g_wT[3 * Cc * Kk * Onc];       // main weights [l][c][k][o]
__device__ float g_woT[3 * Cc * Kk * 28];       // offset weights [l][c][tap][28]

// ---- packed f32x2 helpers -------------------------------------------------
#define FMA2(d, a, b)  asm("fma.rn.f32x2 %0, %1, %2, %0;" : "+l"(d) : "l"(a), "l"(b))
#define ADDP2(d, a)    asm("add.rn.f32x2 %0, %1, %0;" : "+l"(d) : "l"(a))

__device__ __forceinline__ u64 pack2(float lo, float hi) {
    u64 r; asm("mov.b64 %0, {%1,%2};" : "=l"(r) : "f"(lo), "f"(hi)); return r;
}
__device__ __forceinline__ float2 unpack2(u64 v) {
    float2 f; asm("mov.b64 {%0,%1}, %2;" : "=f"(f.x), "=f"(f.y) : "l"(v)); return f;
}

// ---------------------------------------------------------------------------
// Prep: transpose main-conv weights [O][C][3][3] -> [C][9][O]
// ---------------------------------------------------------------------------
__global__ void transpose_w_kernel(const float* __restrict__ w, float* __restrict__ wT)
{
    int idx = blockIdx.x * blockDim.x + threadIdx.x;
    if (idx >= Cc * Kk * Onc) return;
    int o = idx & (Onc - 1);
    int k = (idx >> 8) % Kk;
    int c = idx / (Kk * Onc);
    wT[idx] = w[((size_t)o * Cc + c) * Kk + k];
}

// Prep: transpose offset weights [27][C][3][3] -> [C][9][28] (padded)
__global__ void transpose_woff_kernel(const float* __restrict__ w, float* __restrict__ wT)
{
    int idx = blockIdx.x * blockDim.x + threadIdx.x;
    if (idx >= Cc * Kk * 28) return;
    int oc  = idx % 28;
    int tap = (idx / 28) % Kk;
    int c   = idx / (Kk * 28);
    wT[idx] = (oc < 27) ? w[((size_t)oc * Cc + c) * Kk + tap] : 0.f;
}

// ---------------------------------------------------------------------------
// Dynamic smem layout (bytes), total 110592, 2 CTAs/SM:
//   [0,      9216)  swgt  float4[576]
//   [9216,  18432)  sidx  int4[576]
//   [18432, 64512)  buf0: wsm0 (9216 floats) + ssm0 (2304 floats)
//   [64512,110592)  buf1: wsm1 + ssm1
// Phase-1 overlays: xs[16][120]+wo[16*252] at 18432 (23808 B);
//                   om[2][64][28] at 64512 (14336 B).
// ---------------------------------------------------------------------------
#define SWGT_O  0
#define SIDX_O  9216
#define BUF_O   18432
#define BUFSZ   46080
#define OM_O    64512
#define SMEMSZ  110592

// stage one 4-channel chunk: weights (9216 floats) + samples (2304)
__device__ __forceinline__ void stage_chunk(
    const float* __restrict__ xb4,       // x + (b*Cc + c0)*HW
    const float* __restrict__ wTc,       // wT + c0*2304
    const float4* __restrict__ swgt, const int4* __restrict__ sidx,
    float* __restrict__ wsm, float* __restrict__ ssm, int tid)
{
    const float4* wp4 = (const float4*)wTc;
    float4* wd = (float4*)wsm;
#pragma unroll
    for (int i = 0; i < 9; i++)
        wd[tid + 256 * i] = __ldg(wp4 + tid + 256 * i);
#pragma unroll
    for (int q = 0; q < 9; q++) {
        int i  = tid + 256 * q;
        int cc = i / 576;
        int r  = i - cc * 576;           // tap*64 + p
        float4 wv = swgt[r];
        int4   iv = sidx[r];
        const float* xp = xb4 + (size_t)cc * HW;
        float s = wv.x * __ldg(xp + iv.x) + wv.y * __ldg(xp + iv.y)
                + wv.z * __ldg(xp + iv.z) + wv.w * __ldg(xp + iv.w);
        ssm[i] = s;
    }
}

__global__ __launch_bounds__(256, 2) void dcn_fused_kernel(
    const float* __restrict__ x,
    const float* __restrict__ w_offT,  // [C][9][28]
    const float* __restrict__ b_off,   // [27]
    const float* __restrict__ wT,      // [C][9][O]
    const float* __restrict__ bias,    // [O]
    float* __restrict__ out)
{
    extern __shared__ __align__(16) char smem[];
    float4* swgt = (float4*)(smem + SWGT_O);
    int4*   sidx = (int4*)(smem + SIDX_O);

    int b   = blockIdx.y;
    int t   = blockIdx.x;             // 0..63
    int py0 = (t >> 3) * 8;
    int px0 = (t & 7) * 8;
    int tid = threadIdx.x;

    // ======================== Phase 1: offset conv ========================
    {
        float* xs_s = (float*)(smem + BUF_O);          // [16][120]
        float* wo_s = xs_s + 16 * 120;                 // [16*252]
        float (*om_s)[64][28] = (float (*)[64][28])(smem + OM_O);

        int p   = tid & 63;
        int g   = tid >> 6;           // channel group 0..3
        int ppy = p >> 3;
        int ppx = p & 7;

        u64 aoff2[14];
#pragma unroll
        for (int j = 0; j < 14; j++) aoff2[j] = 0ull;

        for (int r = 0; r < 16; r++) {
            __syncthreads();
            // stage 16 channels' 10x10 halos (rows padded to 12)
            for (int i = tid; i < 1920; i += 256) {
                int ch  = i / 120;
                int rem = i - ch * 120;
                int rr  = rem / 12;
                int cc2 = rem - rr * 12;
                int c   = (r << 4) + ch;
                int gy  = py0 - 1 + rr;
                int gx  = px0 - 1 + cc2;
                float v = 0.f;
                if (cc2 < 10 && (unsigned)gy < (unsigned)Hh && (unsigned)gx < (unsigned)Ww)
                    v = __ldg(x + ((size_t)(b * Cc + c)) * HW + gy * Ww + gx);
                xs_s[ch * 120 + rem] = v;
            }
            // stage 16 channels' pre-transposed offset weights (coalesced)
            {
                const float4* wp4 = (const float4*)(w_offT + (size_t)(r << 4) * 252);
                float4* wo4 = (float4*)wo_s;
                for (int i = tid; i < 1008; i += 256) wo4[i] = __ldg(wp4 + i);
            }
            __syncthreads();

#pragma unroll
            for (int ci = 0; ci < 4; ci++) {
                int ch = (g << 2) + ci;
                const float* xrow = xs_s + ch * 120;
                float xv[9];
#pragma unroll
                for (int rr = 0; rr < 3; rr++)
#pragma unroll
                    for (int cc = 0; cc < 3; cc++)
                        xv[rr * 3 + cc] = xrow[(ppy + rr) * 12 + ppx + cc];

#pragma unroll
                for (int tap = 0; tap < 9; tap++) {
                    u64 xt2 = pack2(xv[tap], xv[tap]);
                    const ulonglong2* wr = (const ulonglong2*)(wo_s + ch * 252 + tap * 28);
#pragma unroll
                    for (int j = 0; j < 7; j++) {
                        ulonglong2 wv2 = wr[j];
                        FMA2(aoff2[2 * j],     xt2, wv2.x);
                        FMA2(aoff2[2 * j + 1], xt2, wv2.y);
                    }
                }
            }
        }
        __syncthreads();
        // two-step cross-group reduction into om[2][64][28]
        if (g >= 2) {
#pragma unroll
            for (int j = 0; j < 14; j++)
                *(u64*)&om_s[g - 2][p][2 * j] = aoff2[j];
        }
        __syncthreads();
        if (g < 2) {
#pragma unroll
            for (int j = 0; j < 14; j++) {
                u64 tacc = *(u64*)&om_s[g][p][2 * j];
                ADDP2(tacc, aoff2[j]);
                *(u64*)&om_s[g][p][2 * j] = tacc;
            }
        }
        __syncthreads();

        // ---- Coordinate / gather-weight precompute ----
        float (*omr)[64][28] = om_s;
        for (int i = tid; i < 576; i += 256) {
            int pp = i & 63;
            int k  = i >> 6;
            int gy = py0 + (pp >> 3);
            int gx = px0 + (pp & 7);
            float dy = __ldg(b_off + 2 * k)     + omr[0][pp][2 * k]     + omr[1][pp][2 * k];
            float dx = __ldg(b_off + 2 * k + 1) + omr[0][pp][2 * k + 1] + omr[1][pp][2 * k + 1];
            float mr = __ldg(b_off + 18 + k)    + omr[0][pp][18 + k]    + omr[1][pp][18 + k];
            float mv = 1.f / (1.f + expf(-mr));
            float ysv = (float)gy + (float)(k / 3 - 1) + dy;
            float xsv = (float)gx + (float)(k % 3 - 1) + dx;
            float y0f = floorf(ysv), x0f = floorf(xsv);
            float wy = ysv - y0f, wx = xsv - x0f;
            int y0 = (int)y0f, x0 = (int)x0f;
            int y1 = y0 + 1, x1 = x0 + 1;
            bool vy0 = (y0 >= 0) && (y0 < Hh);
            bool vy1 = (y1 >= 0) && (y1 < Hh);
            bool vx0 = (x0 >= 0) && (x0 < Ww);
            bool vx1 = (x1 >= 0) && (x1 < Ww);
            int y0c = min(max(y0, 0), Hh - 1), y1c = min(max(y1, 0), Hh - 1);
            int x0c = min(max(x0, 0), Ww - 1), x1c = min(max(x1, 0), Ww - 1);
            float4 wv;
            wv.x = (vy0 && vx0) ? mv * (1.f - wy) * (1.f - wx) : 0.f;
            wv.y = (vy0 && vx1) ? mv * (1.f - wy) * wx         : 0.f;
            wv.z = (vy1 && vx0) ? mv * wy * (1.f - wx)         : 0.f;
            wv.w = (vy1 && vx1) ? mv * wy * wx                 : 0.f;
            int4 iv;
            iv.x = y0c * Ww + x0c;
            iv.y = y0c * Ww + x1c;
            iv.z = y1c * Ww + x0c;
            iv.w = y1c * Ww + x1c;
            swgt[i] = wv;
            sidx[i] = iv;
        }
        __syncthreads();
    }

    // ======= Phase 2: double-buffered sampling + f32x2 GEMM + epilogue =======
    int to = tid >> 4;   // 0..15 -> o-base = to*16
    int tp = tid & 15;   // 0..15 -> p-base = tp*4

    u64 acc2[8][4];
#pragma unroll
    for (int i = 0; i < 8; i++)
#pragma unroll
        for (int j = 0; j < 4; j++) acc2[i][j] = 0ull;

    const float* xb = x + (size_t)b * Cc * HW;
    float* wsmb[2] = {(float*)(smem + BUF_O), (float*)(smem + BUF_O + BUFSZ)};
    float* ssmb[2] = {wsmb[0] + 9216, wsmb[1] + 9216};

    // prologue: stage chunk 0 into buf0
    stage_chunk(xb, wT, swgt, sidx, wsmb[0], ssmb[0], tid);
    __syncthreads();

    for (int j = 0; j < 64; j++) {
        // stage chunk j+1 into the other buffer (LDGs overlap with GEMM below)
        if (j < 63) {
            int c1 = (j + 1) << 2;
            stage_chunk(xb + (size_t)c1 * HW, wT + (size_t)c1 * 2304,
                        swgt, sidx, wsmb[(j + 1) & 1], ssmb[(j + 1) & 1], tid);
        }

        const float* wsm = wsmb[j & 1];
        const float* ssm = ssmb[j & 1];
#pragma unroll 1
        for (int cc = 0; cc < 4; cc++) {
            const float* wbase = wsm + cc * 2304 + (to << 4);
            const float* sbase = ssm + cc * 576 + (tp << 2);
#pragma unroll
            for (int k = 0; k < 9; k++) {
                const float* wr = wbase + k * 256;
                ulonglong2 w01 = *(const ulonglong2*)(wr);
                ulonglong2 w23 = *(const ulonglong2*)(wr + 4);
                ulonglong2 w45 = *(const ulonglong2*)(wr + 8);
                ulonglong2 w67 = *(const ulonglong2*)(wr + 12);
                float4 sv = *(const float4*)(sbase + k * 64);
                u64 sp[4];
                sp[0] = pack2(sv.x, sv.x);
                sp[1] = pack2(sv.y, sv.y);
                sp[2] = pack2(sv.z, sv.z);
                sp[3] = pack2(sv.w, sv.w);
                u64 wp[8] = {w01.x, w01.y, w23.x, w23.y, w45.x, w45.y, w67.x, w67.y};
#pragma unroll
                for (int op = 0; op < 8; op++)
#pragma unroll
                    for (int jj = 0; jj < 4; jj++)
                        FMA2(acc2[op][jj], wp[op], sp[jj]);
            }
        }
        __syncthreads();
    }

    // epilogue: bias + ReLU, vectorized stores
    {
        int row = tp >> 1;
        int cb  = (tp & 1) << 2;
#pragma unroll
        for (int op = 0; op < 8; op++) {
            int o0 = (to << 4) + (op << 1);
            float bv0 = __ldg(bias + o0);
            float bv1 = __ldg(bias + o0 + 1);
            float2 v0 = unpack2(acc2[op][0]);
            float2 v1 = unpack2(acc2[op][1]);
            float2 v2 = unpack2(acc2[op][2]);
            float2 v3 = unpack2(acc2[op][3]);
            float4 lo, hi;
            lo.x = fmaxf(v0.x + bv0, 0.f); lo.y = fmaxf(v1.x + bv0, 0.f);
            lo.z = fmaxf(v2.x + bv0, 0.f); lo.w = fmaxf(v3.x + bv0, 0.f);
            hi.x = fmaxf(v0.y + bv1, 0.f); hi.y = fmaxf(v1.y + bv1, 0.f);
            hi.z = fmaxf(v2.y + bv1, 0.f); hi.w = fmaxf(v3.y + bv1, 0.f);
            size_t base0 = ((size_t)(b * Onc + o0) * Hh + py0 + row) * Ww + px0 + cb;
            size_t base1 = base0 + (size_t)Hh * Ww;
            *(float4*)(out + base0) = lo;
            *(float4*)(out + base1) = hi;
        }
    }
}

// ---------------------------------------------------------------------------
// Launch
// ---------------------------------------------------------------------------
extern "C" void kernel_launch(void* const* d_in, const int* in_sizes, int n_in,
                              void* d_out, int out_size)
{
    const float* x = (const float*)d_in[0];
    const float* w_off[3] = {(const float*)d_in[1], (const float*)d_in[5], (const float*)d_in[9]};
    const float* b_off[3] = {(const float*)d_in[2], (const float*)d_in[6], (const float*)d_in[10]};
    const float* wq[3]    = {(const float*)d_in[3], (const float*)d_in[7], (const float*)d_in[11]};
    const float* bias[3]  = {(const float*)d_in[4], (const float*)d_in[8], (const float*)d_in[12]};

    float *buf1, *buf2, *wT, *woT;
    cudaGetSymbolAddress((void**)&buf1, g_buf1);
    cudaGetSymbolAddress((void**)&buf2, g_buf2);
    cudaGetSymbolAddress((void**)&wT, g_wT);
    cudaGetSymbolAddress((void**)&woT, g_woT);

    cudaFuncSetAttribute(dcn_fused_kernel, cudaFuncAttributeMaxDynamicSharedMemorySize, SMEMSZ);

    for (int l = 0; l < 3; l++) {
        transpose_w_kernel<<<(Cc * Kk * Onc + 255) / 256, 256>>>(wq[l], wT + (size_t)l * Cc * Kk * Onc);
        transpose_woff_kernel<<<(Cc * Kk * 28 + 255) / 256, 256>>>(w_off[l], woT + (size_t)l * Cc * Kk * 28);
    }

    const float* src[3] = {x, buf1, buf2};
    float*       dst[3] = {buf1, buf2, (float*)d_out};

    for (int l = 0; l < 3; l++) {
        dcn_fused_kernel<<<dim3(64, Bn), 256, SMEMSZ>>>(src[l],
                                                        woT + (size_t)l * Cc * Kk * 28,
                                                        b_off[l],
                                                        wT + (size_t)l * Cc * Kk * Onc,
                                                        bias[l], dst[l]);
    }
}

// round 7
// speedup vs baseline: 2.0551x; 1.0219x over previous
#include <cuda_runtime.h>
#include <math.h>
#include <cstdint>

#define Bn 4
#define Cc 256
#define Onc 256
#define Hh 64
#define Ww 64
#define Kk 9
#define HW 4096

typedef unsigned long long u64;
typedef uint32_t u32;

// Scratch (static device arrays — no allocation)
__device__ float g_buf1[Bn * Cc * HW];
__device__ float g_buf2[Bn * Cc * HW];
__device__ float g_wT[3 * Cc * Kk * Onc];       // main weights [l][c][k][o]
__device__ float g_woT[3 * Cc * Kk * 28];       // offset weights [l][c][tap][28]

// ---- packed f32x2 helpers -------------------------------------------------
#define FMA2(d, a, b)  asm("fma.rn.f32x2 %0, %1, %2, %0;" : "+l"(d) : "l"(a), "l"(b))
#define ADDP2(d, a)    asm("add.rn.f32x2 %0, %1, %0;" : "+l"(d) : "l"(a))

__device__ __forceinline__ u64 pack2(float lo, float hi) {
    u64 r; asm("mov.b64 %0, {%1,%2};" : "=l"(r) : "f"(lo), "f"(hi)); return r;
}
__device__ __forceinline__ float2 unpack2(u64 v) {
    float2 f; asm("mov.b64 {%0,%1}, %2;" : "=f"(f.x), "=f"(f.y) : "l"(v)); return f;
}

// ---- cp.async helpers (sm_80+, compiles at compute_103) -------------------
__device__ __forceinline__ u32 smem_u32(const void* p) {
    u32 a;
    asm("{ .reg .u64 t; cvta.to.shared.u64 t, %1; cvt.u32.u64 %0, t; }" : "=r"(a) : "l"(p));
    return a;
}
#define CP_ASYNC16(dst, src) \
    asm volatile("cp.async.cg.shared.global [%0], [%1], 16;" :: "r"(dst), "l"(src))
#define CP_COMMIT() asm volatile("cp.async.commit_group;" ::: "memory")
#define CP_WAIT(n)  asm volatile("cp.async.wait_group %0;" :: "n"(n) : "memory")

// ---------------------------------------------------------------------------
// Prep: transpose main-conv weights [O][C][3][3] -> [C][9][O]
// ---------------------------------------------------------------------------
__global__ void transpose_w_kernel(const float* __restrict__ w, float* __restrict__ wT)
{
    int idx = blockIdx.x * blockDim.x + threadIdx.x;
    if (idx >= Cc * Kk * Onc) return;
    int o = idx & (Onc - 1);
    int k = (idx >> 8) % Kk;
    int c = idx / (Kk * Onc);
    wT[idx] = w[((size_t)o * Cc + c) * Kk + k];
}

// Prep: transpose offset weights [27][C][3][3] -> [C][9][28] (padded)
__global__ void transpose_woff_kernel(const float* __restrict__ w, float* __restrict__ wT)
{
    int idx = blockIdx.x * blockDim.x + threadIdx.x;
    if (idx >= Cc * Kk * 28) return;
    int oc  = idx % 28;
    int tap = (idx / 28) % Kk;
    int c   = idx / (Kk * 28);
    wT[idx] = (oc < 27) ? w[((size_t)oc * Cc + c) * Kk + tap] : 0.f;
}

// ---------------------------------------------------------------------------
// Dynamic smem layout (bytes), total 110592, 2 CTAs/SM:
//   [0,      9216)  swgt  float4[576]
//   [9216,  18432)  sidx  int4[576]
//   [18432, 55296)  wsm buf0  (9216 floats, filled by cp.async)
//   [55296, 92160)  wsm buf1
//   [92160,110592)  ssm2 u64[2304]  (pre-duplicated sample pairs)
// Phase-1 overlays: xs[16][120]+wo[16*252] at 18432; om[2][64][28] at 55296.
// ---------------------------------------------------------------------------
#define SWGT_O  0
#define SIDX_O  9216
#define W0_O    18432
#define W1_O    55296
#define SSM_O   92160
#define OM_O    55296
#define SMEMSZ  110592

__global__ __launch_bounds__(256, 2) void dcn_fused_kernel(
    const float* __restrict__ x,
    const float* __restrict__ w_offT,  // [C][9][28]
    const float* __restrict__ b_off,   // [27]
    const float* __restrict__ wT,      // [C][9][O]
    const float* __restrict__ bias,    // [O]
    float* __restrict__ out)
{
    extern __shared__ __align__(16) char smem[];
    float4* swgt = (float4*)(smem + SWGT_O);
    int4*   sidx = (int4*)(smem + SIDX_O);

    u32 sb  = smem_u32(smem);
    int b   = blockIdx.y;
    int t   = blockIdx.x;             // 0..63
    int py0 = (t >> 3) * 8;
    int px0 = (t & 7) * 8;
    int tid = threadIdx.x;

    // ======================== Phase 1: offset conv ========================
    {
        float* xs_s = (float*)(smem + W0_O);           // [16][120]
        float* wo_s = xs_s + 16 * 120;                 // [16*252]
        float (*om_s)[64][28] = (float (*)[64][28])(smem + OM_O);

        int p   = tid & 63;
        int g   = tid >> 6;           // channel group 0..3
        int ppy = p >> 3;
        int ppx = p & 7;

        u64 aoff2[14];
#pragma unroll
        for (int j = 0; j < 14; j++) aoff2[j] = 0ull;

        for (int r = 0; r < 16; r++) {
            __syncthreads();
            // stage 16 channels' 10x10 halos (rows padded to 12)
            for (int i = tid; i < 1920; i += 256) {
                int ch  = i / 120;
                int rem = i - ch * 120;
                int rr  = rem / 12;
                int cc2 = rem - rr * 12;
                int c   = (r << 4) + ch;
                int gy  = py0 - 1 + rr;
                int gx  = px0 - 1 + cc2;
                float v = 0.f;
                if (cc2 < 10 && (unsigned)gy < (unsigned)Hh && (unsigned)gx < (unsigned)Ww)
                    v = __ldg(x + ((size_t)(b * Cc + c)) * HW + gy * Ww + gx);
                xs_s[ch * 120 + rem] = v;
            }
            // stage 16 channels' pre-transposed offset weights (coalesced)
            {
                const float4* wp4 = (const float4*)(w_offT + (size_t)(r << 4) * 252);
                float4* wo4 = (float4*)wo_s;
                for (int i = tid; i < 1008; i += 256) wo4[i] = __ldg(wp4 + i);
            }
            __syncthreads();

#pragma unroll
            for (int ci = 0; ci < 4; ci++) {
                int ch = (g << 2) + ci;
                const float* xrow = xs_s + ch * 120;
                float xv[9];
#pragma unroll
                for (int rr = 0; rr < 3; rr++)
#pragma unroll
                    for (int cc = 0; cc < 3; cc++)
                        xv[rr * 3 + cc] = xrow[(ppy + rr) * 12 + ppx + cc];

#pragma unroll
                for (int tap = 0; tap < 9; tap++) {
                    u64 xt2 = pack2(xv[tap], xv[tap]);
                    const ulonglong2* wr = (const ulonglong2*)(wo_s + ch * 252 + tap * 28);
#pragma unroll
                    for (int j = 0; j < 7; j++) {
                        ulonglong2 wv2 = wr[j];
                        FMA2(aoff2[2 * j],     xt2, wv2.x);
                        FMA2(aoff2[2 * j + 1], xt2, wv2.y);
                    }
                }
            }
        }
        __syncthreads();
        // two-step cross-group reduction into om[2][64][28]
        if (g >= 2) {
#pragma unroll
            for (int j = 0; j < 14; j++)
                *(u64*)&om_s[g - 2][p][2 * j] = aoff2[j];
        }
        __syncthreads();
        if (g < 2) {
#pragma unroll
            for (int j = 0; j < 14; j++) {
                u64 tacc = *(u64*)&om_s[g][p][2 * j];
                ADDP2(tacc, aoff2[j]);
                *(u64*)&om_s[g][p][2 * j] = tacc;
            }
        }
        __syncthreads();

        // ---- Coordinate / gather-weight precompute ----
        float (*omr)[64][28] = om_s;
        for (int i = tid; i < 576; i += 256) {
            int pp = i & 63;
            int k  = i >> 6;
            int gy = py0 + (pp >> 3);
            int gx = px0 + (pp & 7);
            float dy = __ldg(b_off + 2 * k)     + omr[0][pp][2 * k]     + omr[1][pp][2 * k];
            float dx = __ldg(b_off + 2 * k + 1) + omr[0][pp][2 * k + 1] + omr[1][pp][2 * k + 1];
            float mr = __ldg(b_off + 18 + k)    + omr[0][pp][18 + k]    + omr[1][pp][18 + k];
            float mv = 1.f / (1.f + expf(-mr));
            float ysv = (float)gy + (float)(k / 3 - 1) + dy;
            float xsv = (float)gx + (float)(k % 3 - 1) + dx;
            float y0f = floorf(ysv), x0f = floorf(xsv);
            float wy = ysv - y0f, wx = xsv - x0f;
            int y0 = (int)y0f, x0 = (int)x0f;
            int y1 = y0 + 1, x1 = x0 + 1;
            bool vy0 = (y0 >= 0) && (y0 < Hh);
            bool vy1 = (y1 >= 0) && (y1 < Hh);
            bool vx0 = (x0 >= 0) && (x0 < Ww);
            bool vx1 = (x1 >= 0) && (x1 < Ww);
            int y0c = min(max(y0, 0), Hh - 1), y1c = min(max(y1, 0), Hh - 1);
            int x0c = min(max(x0, 0), Ww - 1), x1c = min(max(x1, 0), Ww - 1);
            float4 wv;
            wv.x = (vy0 && vx0) ? mv * (1.f - wy) * (1.f - wx) : 0.f;
            wv.y = (vy0 && vx1) ? mv * (1.f - wy) * wx         : 0.f;
            wv.z = (vy1 && vx0) ? mv * wy * (1.f - wx)         : 0.f;
            wv.w = (vy1 && vx1) ? mv * wy * wx                 : 0.f;
            int4 iv;
            iv.x = y0c * Ww + x0c;
            iv.y = y0c * Ww + x1c;
            iv.z = y1c * Ww + x0c;
            iv.w = y1c * Ww + x1c;
            swgt[i] = wv;
            sidx[i] = iv;
        }
        __syncthreads();
    }

    // ===== Phase 2: cp.async weights + dup-pair sampling + f32x2 GEMM =====
    int to = tid >> 4;   // 0..15 -> o-base = to*16
    int tp = tid & 15;   // 0..15 -> p-base = tp*4

    u64 acc2[8][4];
#pragma unroll
    for (int i = 0; i < 8; i++)
#pragma unroll
        for (int j = 0; j < 4; j++) acc2[i][j] = 0ull;

    const float* xb = x + (size_t)b * Cc * HW;
    u64* ssm2 = (u64*)(smem + SSM_O);

    // prologue: issue weight cp.async for chunk 0 into buf0
    {
        const float4* wp4 = (const float4*)wT;
        u32 wdst = sb + W0_O + tid * 16;
#pragma unroll
        for (int i = 0; i < 9; i++)
            CP_ASYNC16(wdst + i * 4096, wp4 + tid + 256 * i);
        CP_COMMIT();
    }

    for (int j = 0; j < 64; j++) {
        if (j > 0) __syncthreads();   // GEMM j-1 done: ssm2 + wbuf[(j+1)&1] reusable

        // issue weight cp.async for chunk j+1 (no regs, overlaps sampling)
        if (j < 63) {
            const float4* wp4 = (const float4*)(wT + (size_t)(j + 1) * 4 * 2304);
            u32 wdst = sb + ((j + 1) & 1 ? W1_O : W0_O) + tid * 16;
#pragma unroll
            for (int i = 0; i < 9; i++)
                CP_ASYNC16(wdst + i * 4096, wp4 + tid + 256 * i);
            CP_COMMIT();
        }

        // gather 9 samples for chunk j, store duplicated pairs
        {
            const float* xb4 = xb + (size_t)(j * 4) * HW;
#pragma unroll
            for (int q = 0; q < 9; q++) {
                int i  = tid + 256 * q;
                int cc = i / 576;
                int r  = i - cc * 576;           // tap*64 + p
                float4 wv = swgt[r];
                int4   iv = sidx[r];
                const float* xp = xb4 + (size_t)cc * HW;
                float s = wv.x * __ldg(xp + iv.x) + wv.y * __ldg(xp + iv.y)
                        + wv.z * __ldg(xp + iv.z) + wv.w * __ldg(xp + iv.w);
                ssm2[i] = pack2(s, s);
            }
        }

        if (j < 63) CP_WAIT(1); else CP_WAIT(0);
        __syncthreads();

        const float* wsm = (const float*)(smem + (j & 1 ? W1_O : W0_O));
#pragma unroll 1
        for (int cc = 0; cc < 4; cc++) {
            const float* wbase = wsm + cc * 2304 + (to << 4);
            const u64*   sbase = ssm2 + cc * 576 + (tp << 2);
#pragma unroll
            for (int k = 0; k < 9; k++) {
                const float* wr = wbase + k * 256;
                ulonglong2 w01 = *(const ulonglong2*)(wr);
                ulonglong2 w23 = *(const ulonglong2*)(wr + 4);
                ulonglong2 w45 = *(const ulonglong2*)(wr + 8);
                ulonglong2 w67 = *(const ulonglong2*)(wr + 12);
                ulonglong2 s01 = *(const ulonglong2*)(sbase + k * 64);
                ulonglong2 s23 = *(const ulonglong2*)(sbase + k * 64 + 2);
                u64 sp[4] = {s01.x, s01.y, s23.x, s23.y};
                u64 wp[8] = {w01.x, w01.y, w23.x, w23.y, w45.x, w45.y, w67.x, w67.y};
#pragma unroll
                for (int op = 0; op < 8; op++)
#pragma unroll
                    for (int jj = 0; jj < 4; jj++)
                        FMA2(acc2[op][jj], wp[op], sp[jj]);
            }
        }
    }

    // epilogue: bias + ReLU, vectorized stores
    {
        int row = tp >> 1;
        int cb  = (tp & 1) << 2;
#pragma unroll
        for (int op = 0; op < 8; op++) {
            int o0 = (to << 4) + (op << 1);
            float bv0 = __ldg(bias + o0);
            float bv1 = __ldg(bias + o0 + 1);
            float2 v0 = unpack2(acc2[op][0]);
            float2 v1 = unpack2(acc2[op][1]);
            float2 v2 = unpack2(acc2[op][2]);
            float2 v3 = unpack2(acc2[op][3]);
            float4 lo, hi;
            lo.x = fmaxf(v0.x + bv0, 0.f); lo.y = fmaxf(v1.x + bv0, 0.f);
            lo.z = fmaxf(v2.x + bv0, 0.f); lo.w = fmaxf(v3.x + bv0, 0.f);
            hi.x = fmaxf(v0.y + bv1, 0.f); hi.y = fmaxf(v1.y + bv1, 0.f);
            hi.z = fmaxf(v2.y + bv1, 0.f); hi.w = fmaxf(v3.y + bv1, 0.f);
            size_t base0 = ((size_t)(b * Onc + o0) * Hh + py0 + row) * Ww + px0 + cb;
            size_t base1 = base0 + (size_t)Hh * Ww;
            *(float4*)(out + base0) = lo;
            *(float4*)(out + base1) = hi;
        }
    }
}

// ---------------------------------------------------------------------------
// Launch
// ---------------------------------------------------------------------------
extern "C" void kernel_launch(void* const* d_in, const int* in_sizes, int n_in,
                              void* d_out, int out_size)
{
    const float* x = (const float*)d_in[0];
    const float* w_off[3] = {(const float*)d_in[1], (const float*)d_in[5], (const float*)d_in[9]};
    const float* b_off[3] = {(const float*)d_in[2], (const float*)d_in[6], (const float*)d_in[10]};
    const float* wq[3]    = {(const float*)d_in[3], (const float*)d_in[7], (const float*)d_in[11]};
    const float* bias[3]  = {(const float*)d_in[4], (const float*)d_in[8], (const float*)d_in[12]};

    float *buf1, *buf2, *wT, *woT;
    cudaGetSymbolAddress((void**)&buf1, g_buf1);
    cudaGetSymbolAddress((void**)&buf2, g_buf2);
    cudaGetSymbolAddress((void**)&wT, g_wT);
    cudaGetSymbolAddress((void**)&woT, g_woT);

    cudaFuncSetAttribute(dcn_fused_kernel, cudaFuncAttributeMaxDynamicSharedMemorySize, SMEMSZ);

    for (int l = 0; l < 3; l++) {
        transpose_w_kernel<<<(Cc * Kk * Onc + 255) / 256, 256>>>(wq[l], wT + (size_t)l * Cc * Kk * Onc);
        transpose_woff_kernel<<<(Cc * Kk * 28 + 255) / 256, 256>>>(w_off[l], woT + (size_t)l * Cc * Kk * 28);
    }

    const float* src[3] = {x, buf1, buf2};
    float*       dst[3] = {buf1, buf2, (float*)d_out};

    for (int l = 0; l < 3; l++) {
        dcn_fused_kernel<<<dim3(64, Bn), 256, SMEMSZ>>>(src[l],
                                                        woT + (size_t)l * Cc * Kk * 28,
                                                        b_off[l],
                                                        wT + (size_t)l * Cc * Kk * Onc,
                                                        bias[l], dst[l]);
    }
}